// round 2
// baseline (speedup 1.0000x reference)
#include <cuda_runtime.h>

#define NHID 32

// Folded constants: per hidden unit j, 9 feature coefficients (basis
// {1,c0,s0}x{1,c1,s1}, b1 folded into the constant term), then W2[j][0..1], pad.
__device__ float g_const[NHID * 12];

struct cpx { float x, y; };

__device__ void apply1q(cpx* s, cpx m00, cpx m01, cpx m10, cpx m11, int wire)
{
    int st = 1 << (2 - wire);
    for (int i = 0; i < 8; i++) {
        if (i & st) continue;
        cpx a = s[i], b = s[i + st];
        cpx n0 = { m00.x*a.x - m00.y*a.y + m01.x*b.x - m01.y*b.y,
                   m00.x*a.y + m00.y*a.x + m01.x*b.y + m01.y*b.x };
        cpx n1 = { m10.x*a.x - m10.y*a.y + m11.x*b.x - m11.y*b.y,
                   m10.x*a.y + m10.y*a.x + m11.x*b.y + m11.y*b.x };
        s[i] = n0; s[i + st] = n1;
    }
}

__device__ void applyCRX(cpx* s, float half_t_c, float half_t_s, int ctrl, int tgt)
{
    int cs = 1 << (2 - ctrl), ts = 1 << (2 - tgt);
    float c = half_t_c, sn = half_t_s;
    for (int i = 0; i < 8; i++) {
        if (!(i & cs) || (i & ts)) continue;
        cpx a = s[i], b = s[i + ts];
        s[i]      = { c*a.x + sn*b.y, c*a.y - sn*b.x };
        s[i + ts] = { c*b.x + sn*a.y, c*b.y - sn*a.x };
    }
}

// Thread j builds row j of the folded coefficient table.
__global__ void setup_kernel(const float* __restrict__ theta,
                             const float* __restrict__ W1,
                             const float* __restrict__ b1,
                             const float* __restrict__ W2)
{
    int j = threadIdx.x;
    if (j >= NHID) return;

    cpx V[4][8];
    for (int a = 0; a < 4; a++) {
        cpx s[8];
        for (int i = 0; i < 8; i++) s[i] = {0.f, 0.f};
        s[a * 2] = {1.f, 0.f};
        float c, sn;
        sincosf(0.5f * theta[0], &sn, &c);
        apply1q(s, {c,0.f},{0.f,-sn},{0.f,-sn},{c,0.f}, 0);     // RX w0
        sincosf(0.5f * theta[1], &sn, &c);
        apply1q(s, {c,0.f},{-sn,0.f},{sn,0.f},{c,0.f}, 1);      // RY w1
        sincosf(0.5f * theta[2], &sn, &c);
        apply1q(s, {c,-sn},{0.f,0.f},{0.f,0.f},{c,sn}, 2);      // RZ w2
        sincosf(0.5f * theta[3], &sn, &c);
        applyCRX(s, c, sn, 0, 1);                                // CRX(0,1)
        sincosf(0.5f * theta[4], &sn, &c);
        apply1q(s, {c,0.f},{-sn,0.f},{sn,0.f},{c,0.f}, 2);      // RY w2
        sincosf(0.5f * theta[5], &sn, &c);
        apply1q(s, {c,0.f},{0.f,-sn},{0.f,-sn},{c,0.f}, 1);     // RX w1
        sincosf(0.5f * theta[6], &sn, &c);
        applyCRX(s, c, sn, 1, 2);                                // CRX(1,2)
        sincosf(0.5f * theta[7], &sn, &c);
        apply1q(s, {c,-sn},{0.f,0.f},{0.f,0.f},{c,sn}, 0);      // RZ w0
        for (int k = 0; k < 8; k++)
            V[a][k] = (a >= 2) ? cpx{ s[k].y, -s[k].x } : s[k]; // * (-i)
    }

    float M[4][4];
    for (int a = 0; a < 4; a++)
        for (int b = 0; b < 4; b++) {
            float m = 0.f;
            for (int k = 0; k < 8; k++)
                m += W1[k * NHID + j] * (V[a][k].x * V[b][k].x + V[a][k].y * V[b][k].y);
            M[a][b] = m;
        }

    const float R[2][2][3] = { { {0.5f, 0.5f, 0.f}, {0.f, 0.f, 0.5f} },
                               { {0.f, 0.f, 0.5f}, {0.5f, -0.5f, 0.f} } };
    float K[3][3] = { {0.f,0.f,0.f},{0.f,0.f,0.f},{0.f,0.f,0.f} };
    for (int a = 0; a < 4; a++)
        for (int b = 0; b < 4; b++) {
            int ia = a >> 1, ja = a & 1, ib = b >> 1, jb = b & 1;
            float Mab = M[a][b];
            for (int m = 0; m < 3; m++)
                for (int n = 0; n < 3; n++)
                    K[m][n] += Mab * R[ia][ib][m] * R[ja][jb][n];
        }
    K[0][0] += b1[j];

    for (int t = 0; t < 9; t++) g_const[j * 12 + t] = K[t / 3][t % 3];
    g_const[j * 12 + 9]  = W2[j * 2 + 0];
    g_const[j * 12 + 10] = W2[j * 2 + 1];
    g_const[j * 12 + 11] = 0.f;
}

// ---- packed f32x2 helpers (Blackwell FFMA2 path) ----
typedef unsigned long long u64;
__device__ __forceinline__ u64 pk2(float lo, float hi) {
    u64 r; asm("mov.b64 %0, {%1,%2};" : "=l"(r) : "f"(lo), "f"(hi)); return r;
}
__device__ __forceinline__ void upk2(u64 v, float& lo, float& hi) {
    asm("mov.b64 {%0,%1}, %2;" : "=f"(lo), "=f"(hi) : "l"(v));
}
__device__ __forceinline__ u64 ffma2(u64 a, u64 b, u64 c) {
    u64 d; asm("fma.rn.f32x2 %0, %1, %2, %3;" : "=l"(d) : "l"(a), "l"(b), "l"(c)); return d;
}
__device__ __forceinline__ u64 relu2(u64 v) {
    float lo, hi;
    upk2(v, lo, hi);
    return pk2(fmaxf(lo, 0.f), fmaxf(hi, 0.f));
}

#define SPT 8  // samples per thread (4 packed pairs)

__global__ void __launch_bounds__(256, 2)
qmlp_kernel(const float* __restrict__ x,
            const float* __restrict__ b2,
            float* __restrict__ out, int B)
{
    // Duplicated constant layout per hidden unit j (24 floats = 6 x 16B):
    //   q0 = (K00,K00,K01,K01)  q1 = (K02,K02,K10,K10)  q2 = (K11,K11,K12,K12)
    //   q3 = (K20,K20,K21,K21)  q4 = (K22,K22,W20,W20)  q5 = (W21,W21,pad,pad)
    __shared__ float sd[NHID * 24];
    for (int i = threadIdx.x; i < NHID * 24; i += blockDim.x)
        sd[i] = g_const[(i / 24) * 12 + (i % 24) / 2];
    __syncthreads();

    long long t  = (long long)blockIdx.x * blockDim.x + threadIdx.x;
    long long s0 = t * SPT;
    if (s0 >= B) return;

    float bias0 = __ldg(&b2[0]);
    float bias1 = __ldg(&b2[1]);

    const ulonglong2* kp = reinterpret_cast<const ulonglong2*>(sd);

    if (s0 + SPT <= B) {
        // 8 samples: six coalesced LDG.128 over x[3*s0 .. 3*s0+23]
        float xs[24];
        const float4* xv = reinterpret_cast<const float4*>(x + s0 * 3);
        #pragma unroll
        for (int i = 0; i < 6; i++) {
            float4 v = xv[i];
            xs[i*4+0] = v.x; xs[i*4+1] = v.y; xs[i*4+2] = v.z; xs[i*4+3] = v.w;
        }

        // x2 is a global phase -> irrelevant. Per sample i: x0=xs[3i], x1=xs[3i+1].
        float c0s[SPT], s0s[SPT], c1s[SPT], s1s[SPT];
        #pragma unroll
        for (int i = 0; i < SPT; i++) {
            __sincosf(xs[3*i],     &s0s[i], &c0s[i]);
            __sincosf(xs[3*i + 1], &s1s[i], &c1s[i]);
        }

        // 4 packed pairs: pair p = samples {2p, 2p+1}
        u64 C0[4], S0[4], C1[4], S1[4], O0[4], O1[4];
        u64 biasp0 = pk2(bias0, bias0), biasp1 = pk2(bias1, bias1);
        #pragma unroll
        for (int p = 0; p < 4; p++) {
            C0[p] = pk2(c0s[2*p], c0s[2*p+1]);
            S0[p] = pk2(s0s[2*p], s0s[2*p+1]);
            C1[p] = pk2(c1s[2*p], c1s[2*p+1]);
            S1[p] = pk2(s1s[2*p], s1s[2*p+1]);
            O0[p] = biasp0;
            O1[p] = biasp1;
        }

        #pragma unroll 4
        for (int j = 0; j < NHID; j++) {
            ulonglong2 q0 = kp[j*6+0], q1 = kp[j*6+1], q2 = kp[j*6+2];
            ulonglong2 q3 = kp[j*6+3], q4 = kp[j*6+4], q5 = kp[j*6+5];

            #pragma unroll
            for (int p = 0; p < 4; p++) {
                // Horner-factored: g = t0 + c0*t1 + s0*t2
                u64 t0 = ffma2(C1[p], q0.y, q0.x);
                t0 = ffma2(S1[p], q1.x, t0);
                u64 t1 = ffma2(C1[p], q2.x, q1.y);
                t1 = ffma2(S1[p], q2.y, t1);
                u64 t2 = ffma2(C1[p], q3.y, q3.x);
                t2 = ffma2(S1[p], q4.x, t2);
                u64 g = ffma2(C0[p], t1, t0);
                g = ffma2(S0[p], t2, g);
                u64 h = relu2(g);
                O0[p] = ffma2(h, q4.y, O0[p]);
                O1[p] = ffma2(h, q5.x, O1[p]);
            }
        }

        // out layout [s*2 + ch]; pair p holds samples {2p, 2p+1}
        float4* ov = reinterpret_cast<float4*>(out + s0 * 2);
        #pragma unroll
        for (int p = 0; p < 4; p++) {
            float a0, a1, b0v, b1v;
            upk2(O0[p], a0, b0v);   // ch0 of samples 2p, 2p+1
            upk2(O1[p], a1, b1v);   // ch1 of samples 2p, 2p+1
            float4 w = { a0, a1, b0v, b1v };
            ov[p] = w;
        }
    } else {
        // generic scalar tail (unused when SPT | B)
        for (long long s = s0; s < B; s++) {
            float xx0 = x[s * 3], xx1 = x[s * 3 + 1];
            float cc0, ss0, cc1, ss1;
            __sincosf(xx0, &ss0, &cc0);
            __sincosf(xx1, &ss1, &cc1);
            float o0 = bias0, o1 = bias1;
            for (int j = 0; j < NHID; j++) {
                const float* K = &sd[j * 24];
                float t0 = K[0] + K[2]*cc1 + K[4]*ss1;
                float t1 = K[6] + K[8]*cc1 + K[10]*ss1;
                float t2 = K[12] + K[14]*cc1 + K[16]*ss1;
                float h = fmaxf(t0 + cc0*t1 + ss0*t2, 0.f);
                o0 += h * K[18];
                o1 += h * K[20];
            }
            out[s * 2]     = o0;
            out[s * 2 + 1] = o1;
        }
    }
}

extern "C" void kernel_launch(void* const* d_in, const int* in_sizes, int n_in,
                              void* d_out, int out_size)
{
    const float* x     = (const float*)d_in[0];
    const float* theta = (const float*)d_in[1];
    const float* W1    = (const float*)d_in[2];
    const float* b1    = (const float*)d_in[3];
    const float* W2    = (const float*)d_in[4];
    const float* b2    = (const float*)d_in[5];
    int B = in_sizes[0] / 3;

    setup_kernel<<<1, 32>>>(theta, W1, b1, W2);

    int nthreads = (B + SPT - 1) / SPT;
    int nblocks  = (nthreads + 255) / 256;
    qmlp_kernel<<<nblocks, 256>>>(x, b2, (float*)d_out, B);
}

// round 3
// speedup vs baseline: 1.1174x; 1.1174x over previous
#include <cuda_runtime.h>

#define NHID 32

// Folded constants: per hidden unit j: 9 feature coefficients K (basis
// {1,c0,s0}x{1,c1,s1}, b1 folded into K00), then W2[j][0..1], pad.
__device__ float g_const[NHID * 12];

struct cpx { float x, y; };

__device__ __forceinline__ void apply1q(cpx* s, cpx m00, cpx m01, cpx m10, cpx m11, int wire)
{
    int st = 1 << (2 - wire);
    for (int i = 0; i < 8; i++) {
        if (i & st) continue;
        cpx a = s[i], b = s[i + st];
        cpx n0 = { m00.x*a.x - m00.y*a.y + m01.x*b.x - m01.y*b.y,
                   m00.x*a.y + m00.y*a.x + m01.x*b.y + m01.y*b.x };
        cpx n1 = { m10.x*a.x - m10.y*a.y + m11.x*b.x - m11.y*b.y,
                   m10.x*a.y + m10.y*a.x + m11.x*b.y + m11.y*b.x };
        s[i] = n0; s[i + st] = n1;
    }
}

__device__ __forceinline__ void applyCRX(cpx* s, float c, float sn, int ctrl, int tgt)
{
    int cs = 1 << (2 - ctrl), ts = 1 << (2 - tgt);
    for (int i = 0; i < 8; i++) {
        if (!(i & cs) || (i & ts)) continue;
        cpx a = s[i], b = s[i + ts];
        s[i]      = { c*a.x + sn*b.y, c*a.y - sn*b.x };
        s[i + ts] = { c*b.x + sn*a.y, c*b.y - sn*a.x };
    }
}

// 1 block, 32 threads. Lanes 0-3 build the 4 reachable columns of the fixed
// unitary (j-independent), share via smem; then every lane j folds its row.
__global__ void setup_kernel(const float* __restrict__ theta,
                             const float* __restrict__ W1,
                             const float* __restrict__ b1,
                             const float* __restrict__ W2)
{
    __shared__ cpx Vs[4][8];
    int tid = threadIdx.x;

    if (tid < 4) {
        cpx s[8];
        for (int i = 0; i < 8; i++) s[i] = {0.f, 0.f};
        s[tid * 2] = {1.f, 0.f};
        float c, sn;
        sincosf(0.5f * theta[0], &sn, &c);
        apply1q(s, {c,0.f},{0.f,-sn},{0.f,-sn},{c,0.f}, 0);     // RX w0
        sincosf(0.5f * theta[1], &sn, &c);
        apply1q(s, {c,0.f},{-sn,0.f},{sn,0.f},{c,0.f}, 1);      // RY w1
        sincosf(0.5f * theta[2], &sn, &c);
        apply1q(s, {c,-sn},{0.f,0.f},{0.f,0.f},{c,sn}, 2);      // RZ w2
        sincosf(0.5f * theta[3], &sn, &c);
        applyCRX(s, c, sn, 0, 1);                                // CRX(0,1)
        sincosf(0.5f * theta[4], &sn, &c);
        apply1q(s, {c,0.f},{-sn,0.f},{sn,0.f},{c,0.f}, 2);      // RY w2
        sincosf(0.5f * theta[5], &sn, &c);
        apply1q(s, {c,0.f},{0.f,-sn},{0.f,-sn},{c,0.f}, 1);     // RX w1
        sincosf(0.5f * theta[6], &sn, &c);
        applyCRX(s, c, sn, 1, 2);                                // CRX(1,2)
        sincosf(0.5f * theta[7], &sn, &c);
        apply1q(s, {c,-sn},{0.f,0.f},{0.f,0.f},{c,sn}, 0);      // RZ w0
        // fold -i from RX(x0)|0> lower branch (columns 2,3)
        for (int k = 0; k < 8; k++)
            Vs[tid][k] = (tid >= 2) ? cpx{ s[k].y, -s[k].x } : s[k];
    }
    __syncwarp();

    int j = tid;
    // M[a][b] = sum_k W1[k,j] * Re(V_a[k] conj(V_b[k]))
    float M[4][4];
    for (int a = 0; a < 4; a++)
        for (int b = 0; b < 4; b++) {
            float m = 0.f;
            for (int k = 0; k < 8; k++)
                m += W1[k * NHID + j] * (Vs[a][k].x * Vs[b][k].x + Vs[a][k].y * Vs[b][k].y);
            M[a][b] = m;
        }

    // Half-angle products over basis (1, cos, sin): p^2=(1+c)/2, pq=s/2, q^2=(1-c)/2
    const float R[2][2][3] = { { {0.5f, 0.5f, 0.f}, {0.f, 0.f, 0.5f} },
                               { {0.f, 0.f, 0.5f}, {0.5f, -0.5f, 0.f} } };
    float K[3][3] = { {0.f,0.f,0.f},{0.f,0.f,0.f},{0.f,0.f,0.f} };
    for (int a = 0; a < 4; a++)
        for (int b = 0; b < 4; b++) {
            int ia = a >> 1, ja = a & 1, ib = b >> 1, jb = b & 1;
            float Mab = M[a][b];
            for (int m = 0; m < 3; m++)
                for (int n = 0; n < 3; n++)
                    K[m][n] += Mab * R[ia][ib][m] * R[ja][jb][n];
        }
    K[0][0] += b1[j];

    for (int t = 0; t < 9; t++) g_const[j * 12 + t] = K[t / 3][t % 3];
    g_const[j * 12 + 9]  = W2[j * 2 + 0];
    g_const[j * 12 + 10] = W2[j * 2 + 1];
    g_const[j * 12 + 11] = 0.f;
}

// ---- packed f32x2 helpers (Blackwell FFMA2 path) ----
typedef unsigned long long u64;
__device__ __forceinline__ u64 pk2(float lo, float hi) {
    u64 r; asm("mov.b64 %0, {%1,%2};" : "=l"(r) : "f"(lo), "f"(hi)); return r;
}
__device__ __forceinline__ void upk2(u64 v, float& lo, float& hi) {
    asm("mov.b64 {%0,%1}, %2;" : "=f"(lo), "=f"(hi) : "l"(v));
}
__device__ __forceinline__ u64 ffma2(u64 a, u64 b, u64 c) {
    u64 d; asm("fma.rn.f32x2 %0, %1, %2, %3;" : "=l"(d) : "l"(a), "l"(b), "l"(c)); return d;
}
__device__ __forceinline__ u64 relu2(u64 v) {
    float lo, hi;
    upk2(v, lo, hi);
    return pk2(fmaxf(lo, 0.f), fmaxf(hi, 0.f));
}

// SPT=4: 2 packed pairs per thread. Horner form keeps the live register set
// small (4 feature u64 per pair) so 4 blocks/SM fit at <=64 regs.
__global__ void __launch_bounds__(256, 4)
qmlp_kernel(const float* __restrict__ x,
            const float* __restrict__ b2,
            float* __restrict__ out, int B)
{
    // Duplicated constant layout per j (24 floats = 6 x 16B), vec v holds
    // consts 2v,2v+1 duplicated:
    //   q0=(K00d,K01d) q1=(K02d,K10d) q2=(K11d,K12d)
    //   q3=(K20d,K21d) q4=(K22d,W20d) q5=(W21d,pad)
    __shared__ float sd[NHID * 24];
    for (int i = threadIdx.x; i < NHID * 24; i += blockDim.x)
        sd[i] = g_const[(i / 24) * 12 + (i % 24) / 2];
    __syncthreads();

    int t  = blockIdx.x * blockDim.x + threadIdx.x;
    int s0 = t * 4;
    if (s0 >= B) return;

    float bias0 = __ldg(&b2[0]);
    float bias1 = __ldg(&b2[1]);

    const ulonglong2* kp = reinterpret_cast<const ulonglong2*>(sd);

    if (s0 + 4 <= B) {
        // 4 samples: three coalesced LDG.128; x2 is a global phase (unused)
        const float4* xv = reinterpret_cast<const float4*>(x + (size_t)s0 * 3);
        float4 XA = xv[0], XB = xv[1], XC = xv[2];
        float x0v[4] = { XA.x, XA.w, XB.z, XC.y };
        float x1v[4] = { XA.y, XB.x, XB.w, XC.z };

        float c0[4], sn0[4], c1[4], sn1[4];
        #pragma unroll
        for (int i = 0; i < 4; i++) {
            __sincosf(x0v[i], &sn0[i], &c0[i]);
            __sincosf(x1v[i], &sn1[i], &c1[i]);
        }

        u64 C0a = pk2(c0[0],  c0[1]),  C0b = pk2(c0[2],  c0[3]);
        u64 S0a = pk2(sn0[0], sn0[1]), S0b = pk2(sn0[2], sn0[3]);
        u64 C1a = pk2(c1[0],  c1[1]),  C1b = pk2(c1[2],  c1[3]);
        u64 S1a = pk2(sn1[0], sn1[1]), S1b = pk2(sn1[2], sn1[3]);

        u64 O0a = pk2(bias0, bias0), O1a = pk2(bias1, bias1);
        u64 O0b = O0a, O1b = O1a;

        #pragma unroll 4
        for (int j = 0; j < NHID; j++) {
            ulonglong2 q0 = kp[j*6+0], q1 = kp[j*6+1];
            ulonglong2 q2 = kp[j*6+2], q3 = kp[j*6+3];

            // Horner: g = t0 + c0*t1 + s0*t2,  t_i = K_i0 + c1*K_i1 + s1*K_i2
            u64 t0a = ffma2(C1a, q0.y, q0.x);  t0a = ffma2(S1a, q1.x, t0a);
            u64 t1a = ffma2(C1a, q2.x, q1.y);  t1a = ffma2(S1a, q2.y, t1a);
            u64 t0b = ffma2(C1b, q0.y, q0.x);  t0b = ffma2(S1b, q1.x, t0b);
            u64 t1b = ffma2(C1b, q2.x, q1.y);  t1b = ffma2(S1b, q2.y, t1b);

            ulonglong2 q4 = kp[j*6+4], q5 = kp[j*6+5];

            u64 t2a = ffma2(C1a, q3.y, q3.x);  t2a = ffma2(S1a, q4.x, t2a);
            u64 t2b = ffma2(C1b, q3.y, q3.x);  t2b = ffma2(S1b, q4.x, t2b);

            u64 ga = ffma2(C0a, t1a, t0a);  ga = ffma2(S0a, t2a, ga);
            u64 gb = ffma2(C0b, t1b, t0b);  gb = ffma2(S0b, t2b, gb);

            u64 ha = relu2(ga), hb = relu2(gb);

            O0a = ffma2(ha, q4.y, O0a);  O1a = ffma2(ha, q5.x, O1a);
            O0b = ffma2(hb, q4.y, O0b);  O1b = ffma2(hb, q5.x, O1b);
        }

        float r00, r01, r10, r11;
        upk2(O0a, r00, r10);   // ch0 of samples 0,1
        upk2(O1a, r01, r11);   // ch1 of samples 0,1
        float4 w0 = { r00, r01, r10, r11 };
        upk2(O0b, r00, r10);
        upk2(O1b, r01, r11);
        float4 w1 = { r00, r01, r10, r11 };
        float4* ov = reinterpret_cast<float4*>(out + (size_t)s0 * 2);
        ov[0] = w0;
        ov[1] = w1;
    } else {
        // generic scalar tail (unused when 4 | B)
        for (int s = s0; s < B; s++) {
            float xx0 = x[(size_t)s * 3], xx1 = x[(size_t)s * 3 + 1];
            float cc0, ss0, cc1, ss1;
            __sincosf(xx0, &ss0, &cc0);
            __sincosf(xx1, &ss1, &cc1);
            float o0 = bias0, o1 = bias1;
            for (int j = 0; j < NHID; j++) {
                const float* K = &sd[j * 24];
                float t0 = K[0]  + K[2]*cc1  + K[4]*ss1;
                float t1 = K[6]  + K[8]*cc1  + K[10]*ss1;
                float t2 = K[12] + K[14]*cc1 + K[16]*ss1;
                float h = fmaxf(t0 + cc0*t1 + ss0*t2, 0.f);
                o0 += h * K[18];
                o1 += h * K[20];
            }
            out[(size_t)s * 2]     = o0;
            out[(size_t)s * 2 + 1] = o1;
        }
    }
}

extern "C" void kernel_launch(void* const* d_in, const int* in_sizes, int n_in,
                              void* d_out, int out_size)
{
    const float* x     = (const float*)d_in[0];
    const float* theta = (const float*)d_in[1];
    const float* W1    = (const float*)d_in[2];
    const float* b1    = (const float*)d_in[3];
    const float* W2    = (const float*)d_in[4];
    const float* b2    = (const float*)d_in[5];
    int B = in_sizes[0] / 3;

    setup_kernel<<<1, 32>>>(theta, W1, b1, W2);

    int nthreads = (B + 3) / 4;
    int nblocks  = (nthreads + 255) / 256;
    qmlp_kernel<<<nblocks, 256>>>(x, b2, (float*)d_out, B);
}